// round 3
// baseline (speedup 1.0000x reference)
#include <cuda_runtime.h>
#include <cstdint>

// N=100000 candidates, OBS=16, FEAT=96 -> ROW=1536 floats per candidate.
// target_vels row = 25*96 = 2400 floats.
#define ROW_F       1536
#define ROW_F4      (ROW_F / 4)       // 384 float4
#define F4_PER_LANE (ROW_F4 / 32)     // 12
#define OUT_F       2400
#define WARPS_PER_BLOCK 8
#define THREADS     256

// One wave: 148 SMs x 8 blocks/SM (2048 threads / 256)
#define GRID_BLOCKS 1184

// Persistent device state; last block restores it every call so kernel_launch
// stays deterministic across graph replays.
__device__ unsigned long long g_best = 0xFFFFFFFFFFFFFFFFULL;
__device__ unsigned int       g_done = 0u;

__global__ __launch_bounds__(THREADS) void nn_persist_kernel(
    const float* __restrict__ in_pose,
    const float* __restrict__ train,
    const float* __restrict__ target_vels,
    float* __restrict__ out,
    int N)
{
    __shared__ float4 s_q[ROW_F4];
    __shared__ unsigned long long s_best[WARPS_PER_BLOCK];
    __shared__ unsigned int s_last;
    __shared__ unsigned int s_bestidx;

    const int tid  = threadIdx.x;
    const int warp = tid >> 5;
    const int lane = tid & 31;

    // stage query (6 KB) into shared, once
    for (int i = tid; i < ROW_F4; i += THREADS)
        s_q[i] = reinterpret_cast<const float4*>(in_pose)[i];
    __syncthreads();

    const int gwarp      = blockIdx.x * WARPS_PER_BLOCK + warp;
    const int warp_count = GRID_BLOCKS * WARPS_PER_BLOCK;   // 9472

    // register-resident running min, packed (dist_bits << 32) | idx.
    // dist >= 0 -> IEEE bits order-preserving; ties break to smallest idx.
    unsigned long long best = 0xFFFFFFFFFFFFFFFFULL;

    for (int cand = gwarp; cand < N; cand += warp_count) {
        const float4* row = reinterpret_cast<const float4*>(train) + (size_t)cand * ROW_F4;
        float acc = 0.f;
        #pragma unroll
        for (int j = 0; j < F4_PER_LANE; j++) {
            const int idx = j * 32 + lane;
            float4 a = row[idx];
            float4 q = s_q[idx];
            float dx = a.x - q.x;
            float dy = a.y - q.y;
            float dz = a.z - q.z;
            float dw = a.w - q.w;
            acc += dx * dx + dy * dy + dz * dz + dw * dw;
        }
        #pragma unroll
        for (int o = 16; o > 0; o >>= 1)
            acc += __shfl_xor_sync(0xFFFFFFFFu, acc, o);
        unsigned long long packed =
            ((unsigned long long)__float_as_uint(acc) << 32) | (unsigned)cand;
        best = min(best, packed);
    }

    if (lane == 0) s_best[warp] = best;
    __syncthreads();

    // block reduce 8 -> 1, one global atomic per block (1184 total)
    if (tid == 0) {
        unsigned long long b = s_best[0];
        #pragma unroll
        for (int w = 1; w < WARPS_PER_BLOCK; w++) b = min(b, s_best[w]);
        atomicMin(&g_best, b);
        __threadfence();
        s_last = (atomicAdd(&g_done, 1u) == (unsigned)GRID_BLOCKS - 1u);
    }
    __syncthreads();

    if (s_last) {
        if (tid == 0) {
            unsigned long long b = atomicAdd(&g_best, 0ULL);  // coherent read
            s_bestidx = (unsigned)(b & 0xFFFFFFFFULL);
        }
        __syncthreads();

        const float* src = target_vels + (size_t)s_bestidx * OUT_F;
        for (int i = tid; i < OUT_F; i += THREADS)
            out[i] = src[i];

        __syncthreads();
        if (tid == 0) {  // restore state for the next replay
            atomicExch(&g_best, 0xFFFFFFFFFFFFFFFFULL);
            atomicExch(&g_done, 0u);
        }
    }
}

extern "C" void kernel_launch(void* const* d_in, const int* in_sizes, int n_in,
                              void* d_out, int out_size)
{
    const float* in_pose     = (const float*)d_in[0];   // [16, 96]
    const float* train_poses = (const float*)d_in[1];   // [N, 16, 96]
    const float* target_vels = (const float*)d_in[2];   // [N, 25, 96]
    float* out = (float*)d_out;                          // [25, 96]

    const int N = in_sizes[1] / ROW_F;

    nn_persist_kernel<<<GRID_BLOCKS, THREADS>>>(in_pose, train_poses, target_vels, out, N);
}

// round 4
// speedup vs baseline: 1.0832x; 1.0832x over previous
#include <cuda_runtime.h>
#include <cstdint>

// N=100000 candidates, OBS=16, FEAT=96 -> ROW=1536 floats per candidate.
// target_vels row = 25*96 = 2400 floats.
#define ROW_F       1536
#define ROW_F4      (ROW_F / 4)       // 384 float4
#define F4_PER_LANE (ROW_F4 / 32)     // 12
#define OUT_F       2400
#define WARPS_PER_BLOCK 8

__device__ unsigned long long g_best;

__global__ void nn_init_kernel() {
    g_best = 0xFFFFFFFFFFFFFFFFULL;
}

// One warp per candidate; 8 warps/block; 32 regs pinned for full occupancy.
__global__ __launch_bounds__(256, 8) void nn_dist_kernel(
    const float* __restrict__ in_pose,
    const float* __restrict__ train,
    int N)
{
    __shared__ float4 s_q[ROW_F4];
    __shared__ unsigned long long s_best[WARPS_PER_BLOCK];

    const int tid  = threadIdx.x;
    const int warp = tid >> 5;
    const int lane = tid & 31;

    // stage query (6 KB) into shared
    for (int i = tid; i < ROW_F4; i += blockDim.x)
        s_q[i] = reinterpret_cast<const float4*>(in_pose)[i];
    __syncthreads();

    const int cand = blockIdx.x * WARPS_PER_BLOCK + warp;
    unsigned long long packed = 0xFFFFFFFFFFFFFFFFULL;

    if (cand < N) {
        const float4* row = reinterpret_cast<const float4*>(train) + (size_t)cand * ROW_F4;
        float acc = 0.f;
        #pragma unroll
        for (int j = 0; j < F4_PER_LANE; j++) {
            const int idx = j * 32 + lane;
            float4 a = __ldcs(&row[idx]);   // streaming: single-use, evict-first
            float4 q = s_q[idx];
            float dx = a.x - q.x;
            float dy = a.y - q.y;
            float dz = a.z - q.z;
            float dw = a.w - q.w;
            acc += dx * dx + dy * dy + dz * dz + dw * dw;
        }
        // warp sum
        #pragma unroll
        for (int o = 16; o > 0; o >>= 1)
            acc += __shfl_xor_sync(0xFFFFFFFFu, acc, o);
        // acc >= 0 -> IEEE bits order-preserving; low 32 = index, so u64 min
        // ties break to the SMALLEST index (jnp.argmin first-min semantics).
        packed = ((unsigned long long)__float_as_uint(acc) << 32) | (unsigned)cand;
    }

    if (lane == 0) s_best[warp] = packed;
    __syncthreads();

    // block reduce 8 -> 1, one global atomic per block
    if (tid == 0) {
        unsigned long long b = s_best[0];
        #pragma unroll
        for (int w = 1; w < WARPS_PER_BLOCK; w++) b = min(b, s_best[w]);
        atomicMin(&g_best, b);
    }
}

__global__ void nn_gather_kernel(const float* __restrict__ target_vels,
                                 float* __restrict__ out)
{
    const unsigned best = (unsigned)(g_best & 0xFFFFFFFFULL);
    const float* src = target_vels + (size_t)best * OUT_F;
    for (int i = threadIdx.x; i < OUT_F; i += blockDim.x)
        out[i] = src[i];
}

extern "C" void kernel_launch(void* const* d_in, const int* in_sizes, int n_in,
                              void* d_out, int out_size)
{
    const float* in_pose     = (const float*)d_in[0];   // [16, 96]
    const float* train_poses = (const float*)d_in[1];   // [N, 16, 96]
    const float* target_vels = (const float*)d_in[2];   // [N, 25, 96]
    float* out = (float*)d_out;                          // [25, 96]

    const int N = in_sizes[1] / ROW_F;

    nn_init_kernel<<<1, 1>>>();
    const int blocks = (N + WARPS_PER_BLOCK - 1) / WARPS_PER_BLOCK;
    nn_dist_kernel<<<blocks, 256>>>(in_pose, train_poses, N);
    nn_gather_kernel<<<1, 256>>>(target_vels, out);
}

// round 5
// speedup vs baseline: 1.1109x; 1.0256x over previous
#include <cuda_runtime.h>
#include <cstdint>

// N=100000 candidates, OBS=16, FEAT=96 -> ROW=1536 floats per candidate.
// target_vels row = 25*96 = 2400 floats.
#define ROW_F       1536
#define ROW_F4      (ROW_F / 4)       // 384 float4
#define F4_PER_LANE (ROW_F4 / 32)     // 12
#define OUT_F       2400
#define WARPS_PER_BLOCK 8

// Statically initialized for the first (uncaptured) correctness call; the
// gather kernel (last in stream order) resets it after use, so every graph
// replay starts clean. No init launch needed.
__device__ unsigned long long g_best = 0xFFFFFFFFFFFFFFFFULL;

// One warp per candidate; 8 warps/block; 32 regs pinned for full occupancy.
__global__ __launch_bounds__(256, 8) void nn_dist_kernel(
    const float* __restrict__ in_pose,
    const float* __restrict__ train,
    int N)
{
    __shared__ float4 s_q[ROW_F4];
    __shared__ unsigned long long s_best[WARPS_PER_BLOCK];

    const int tid  = threadIdx.x;
    const int warp = tid >> 5;
    const int lane = tid & 31;

    // stage query (6 KB) into shared
    for (int i = tid; i < ROW_F4; i += blockDim.x)
        s_q[i] = reinterpret_cast<const float4*>(in_pose)[i];
    __syncthreads();

    const int cand = blockIdx.x * WARPS_PER_BLOCK + warp;
    unsigned long long packed = 0xFFFFFFFFFFFFFFFFULL;

    if (cand < N) {
        const float4* row = reinterpret_cast<const float4*>(train) + (size_t)cand * ROW_F4;
        float acc = 0.f;
        #pragma unroll
        for (int j = 0; j < F4_PER_LANE; j++) {
            const int idx = j * 32 + lane;
            float4 a = row[idx];
            float4 q = s_q[idx];
            float dx = a.x - q.x;
            float dy = a.y - q.y;
            float dz = a.z - q.z;
            float dw = a.w - q.w;
            acc += dx * dx + dy * dy + dz * dz + dw * dw;
        }
        // warp sum
        #pragma unroll
        for (int o = 16; o > 0; o >>= 1)
            acc += __shfl_xor_sync(0xFFFFFFFFu, acc, o);
        // acc >= 0 -> IEEE bits order-preserving; low 32 = index, so u64 min
        // ties break to the SMALLEST index (jnp.argmin first-min semantics).
        packed = ((unsigned long long)__float_as_uint(acc) << 32) | (unsigned)cand;
    }

    if (lane == 0) s_best[warp] = packed;
    __syncthreads();

    // block reduce 8 -> 1, one global atomic per block
    if (tid == 0) {
        unsigned long long b = s_best[0];
        #pragma unroll
        for (int w = 1; w < WARPS_PER_BLOCK; w++) b = min(b, s_best[w]);
        atomicMin(&g_best, b);
    }
}

// Single block: gather the winning row, then reset g_best for the next replay.
__global__ void nn_gather_kernel(const float* __restrict__ target_vels,
                                 float* __restrict__ out)
{
    __shared__ unsigned int s_bestidx;
    if (threadIdx.x == 0)
        s_bestidx = (unsigned)(g_best & 0xFFFFFFFFULL);
    __syncthreads();

    const float* src = target_vels + (size_t)s_bestidx * OUT_F;
    for (int i = threadIdx.x; i < OUT_F; i += blockDim.x)
        out[i] = src[i];

    __syncthreads();
    if (threadIdx.x == 0)
        g_best = 0xFFFFFFFFFFFFFFFFULL;   // clean state for next replay
}

extern "C" void kernel_launch(void* const* d_in, const int* in_sizes, int n_in,
                              void* d_out, int out_size)
{
    const float* in_pose     = (const float*)d_in[0];   // [16, 96]
    const float* train_poses = (const float*)d_in[1];   // [N, 16, 96]
    const float* target_vels = (const float*)d_in[2];   // [N, 25, 96]
    float* out = (float*)d_out;                          // [25, 96]

    const int N = in_sizes[1] / ROW_F;

    const int blocks = (N + WARPS_PER_BLOCK - 1) / WARPS_PER_BLOCK;
    nn_dist_kernel<<<blocks, 256>>>(in_pose, train_poses, N);
    nn_gather_kernel<<<1, 256>>>(target_vels, out);
}